// round 7
// baseline (speedup 1.0000x reference)
#include <cuda_runtime.h>
#include <cuda_fp16.h>
#include <cstdint>

#define EMB   1024
#define NB    4
#define SEQ   4096
#define NROWS (NB*SEQ)   // 16384

#define BM    128        // CTA M tile
#define BN    256        // CTA N tile
#define BKH   64         // K halves per stage (4 x k16)
#define SROWW 36         // smem row stride in words; 36%32==4 -> conflict-free frags
#define NKS   4          // k16 steps per stage
#define NSTG  3          // pipeline stages

// fp16 scratch (device globals: allocation-free per harness rules)
__device__ __align__(1024) __half g_xh [(size_t)NROWS*EMB];
__device__ __align__(1024) __half g_wqh[(size_t)EMB*EMB];
__device__ __align__(1024) __half g_wkh[(size_t)EMB*EMB];
__device__ __align__(1024) __half g_wvh[(size_t)EMB*EMB];
__device__ __align__(1024) __half g_qh [(size_t)NB*SEQ*EMB];
__device__ __align__(1024) __half g_kh [(size_t)NB*SEQ*EMB];
__device__ __align__(1024) __half g_vth[(size_t)NB*SEQ*EMB];   // Vt[E, B*S]
__device__ __align__(1024) __half g_sh [(size_t)NB*SEQ*SEQ];   // scores / probs

__device__ __forceinline__ unsigned packh2(float x, float y){
    __half2 h = __floats2half2_rn(x, y);
    return *reinterpret_cast<unsigned*>(&h);
}
__device__ __forceinline__ float2 h2f2(unsigned u){
    __half2 h = *reinterpret_cast<__half2*>(&u);
    return __half22float2(h);
}
__device__ __forceinline__ uint32_t smem_u32(const void* p){
    uint32_t a;
    asm("{ .reg .u64 t; cvta.to.shared.u64 t, %1; cvt.u32.u64 %0, t; }" : "=r"(a) : "l"(p));
    return a;
}
__device__ __forceinline__ void cp16(uint32_t s, const void* g){
    asm volatile("cp.async.ca.shared.global [%0], [%1], 16;" :: "r"(s), "l"(g));
}
#define CP_COMMIT() asm volatile("cp.async.commit_group;" ::: "memory")
#define CP_WAIT(N)  asm volatile("cp.async.wait_group %0;" :: "n"(N) : "memory")

__device__ __forceinline__ void ldsm4(unsigned& r0, unsigned& r1, unsigned& r2, unsigned& r3,
                                      uint32_t addr){
    asm volatile("ldmatrix.sync.aligned.m8n8.x4.shared.b16 {%0,%1,%2,%3}, [%4];"
        : "=r"(r0), "=r"(r1), "=r"(r2), "=r"(r3) : "r"(addr));
}

__device__ __forceinline__ void mma16816(float c[4], const unsigned a[4],
                                         unsigned b0, unsigned b1){
    asm volatile(
        "mma.sync.aligned.m16n8k16.row.col.f32.f16.f16.f32 "
        "{%0,%1,%2,%3},{%4,%5,%6,%7},{%8,%9},{%0,%1,%2,%3};"
        : "+f"(c[0]), "+f"(c[1]), "+f"(c[2]), "+f"(c[3])
        : "r"(a[0]), "r"(a[1]), "r"(a[2]), "r"(a[3]), "r"(b0), "r"(b1));
}

// C[M,N] = A[M,K] * B[N,K]^T (+bias). All-fp16 inputs, K-major, fp32 accum.
// OH: output half (else float). bias_mode: 0 none, 1 col bias[n], 2 row bias[m].
// bko: per-batch offset into B's K dimension (PV slicing of Vt).
template<bool OH>
__global__ void __launch_bounds__(256,1) gemm_h2(
    const __half* __restrict__ A, int lda, long long sA,
    const __half* __restrict__ B, int ldb, long long sB,
    const float* __restrict__ bias, int bias_mode,
    void* __restrict__ C_, int ldc, long long sC,
    int K, int bko)
{
    extern __shared__ __align__(16) unsigned sm[];
    const uint32_t sbase = smem_u32(sm);
    const uint32_t BOFFW = NSTG*BM*SROWW;   // B region word offset (after NSTG A stages)

    const int z  = blockIdx.z;
    const int m0 = blockIdx.y * BM;
    const int n0 = blockIdx.x * BN;
    const int tid  = threadIdx.x;
    const int lane = tid & 31;
    const int wid  = tid >> 5;
    const int qd   = lane & 3;             // 0..3
    const int wm0  = (wid >> 2) * 64;      // warp rows: 2 x 64
    const int wn0  = (wid & 3) * 64;       // warp cols: 4 x 64

    const __half* A0 = A + (size_t)z*sA + (size_t)m0*lda;
    const __half* B0 = B + (size_t)z*sB + (size_t)n0*ldb + (size_t)z*bko;

    // ldmatrix per-lane byte addresses (stage-0 base; add stage/k offsets later)
    const uint32_t aAddr0 = sbase + (uint32_t)(((wm0 + (lane & 15))*SROWW) * 4) + ((lane >> 4) * 16);
    const uint32_t bAddr0 = sbase + (BOFFW + (uint32_t)(wn0 + ((lane >> 4) * 8) + (lane & 7))*SROWW) * 4
                          + (((lane >> 3) & 1) * 16);

    float c[4][8][4];
    #pragma unroll
    for (int mi = 0; mi < 4; mi++)
        #pragma unroll
        for (int ni = 0; ni < 8; ni++)
            #pragma unroll
            for (int j = 0; j < 4; j++) c[mi][ni][j] = 0.f;

    const int KT = K / BKH;

    auto issue = [&](int kt, int s){
        #pragma unroll
        for (int i = 0; i < 4; i++){                 // A: 128 rows x 8 chunks / 256 thr
            const int id = tid + 256*i;
            const int row = id >> 3, ch = id & 7;
            cp16(sbase + (s*BM*SROWW + row*SROWW + ch*4)*4,
                 A0 + (size_t)row*lda + kt*BKH + ch*8);
        }
        #pragma unroll
        for (int i = 0; i < 8; i++){                 // B: 256 rows x 8 chunks / 256 thr
            const int id = tid + 256*i;
            const int row = id >> 3, ch = id & 7;
            cp16(sbase + (BOFFW + s*BN*SROWW + row*SROWW + ch*4)*4,
                 B0 + (size_t)row*ldb + kt*BKH + ch*8);
        }
        CP_COMMIT();
    };

    issue(0, 0);
    issue(1, 1);

    unsigned af[2][4][4];   // A frag double buffer: [buf][mi][reg]
    unsigned bf[2][4];      // B frag double buffer: [buf][reg]

    int stg = 0;                       // kt % NSTG
    int stg2 = 2;                      // (kt+2) % NSTG
    for (int kt = 0; kt < KT; kt++){
        if (kt < KT-1) CP_WAIT(1); else CP_WAIT(0);
        __syncthreads();
        if (kt + 2 < KT) issue(kt + 2, stg2);

        const uint32_t aS = aAddr0 + (uint32_t)stg * (BM*SROWW*4);
        const uint32_t bS = bAddr0 + (uint32_t)stg * (BN*SROWW*4);

        // preload ks=0 fragments
        #pragma unroll
        for (int mi = 0; mi < 4; mi++)
            ldsm4(af[0][mi][0], af[0][mi][1], af[0][mi][2], af[0][mi][3],
                  aS + (uint32_t)(mi*16*SROWW*4));
        ldsm4(bf[0][0], bf[0][1], bf[0][2], bf[0][3], bS);

        #pragma unroll
        for (int ks = 0; ks < NKS; ks++){
            const int cab = ks & 1;
            const uint32_t ko  = (uint32_t)(ks * 32);        // 8 words per k16 step
            #pragma unroll
            for (int np = 0; np < 4; np++){
                const int cb = np & 1;
                // prefetch next B fragment pair
                if (np < 3)
                    ldsm4(bf[cb^1][0], bf[cb^1][1], bf[cb^1][2], bf[cb^1][3],
                          bS + (uint32_t)((np+1)*16*SROWW*4) + ko);
                else if (ks < NKS-1)
                    ldsm4(bf[cb^1][0], bf[cb^1][1], bf[cb^1][2], bf[cb^1][3],
                          bS + ko + 32);
                // prefetch next ks A fragments (once per ks)
                if (np == 0 && ks < NKS-1){
                    #pragma unroll
                    for (int mi = 0; mi < 4; mi++)
                        ldsm4(af[cab^1][mi][0], af[cab^1][mi][1],
                              af[cab^1][mi][2], af[cab^1][mi][3],
                              aS + (uint32_t)(mi*16*SROWW*4) + ko + 32);
                }
                #pragma unroll
                for (int mi = 0; mi < 4; mi++){
                    mma16816(c[mi][2*np  ], af[cab][mi], bf[cb][0], bf[cb][1]);
                    mma16816(c[mi][2*np+1], af[cab][mi], bf[cb][2], bf[cb][3]);
                }
            }
        }

        if (++stg  == NSTG) stg  = 0;
        if (++stg2 == NSTG) stg2 = 0;
    }

    // epilogue: c0->(r,cc) c1->(r,cc+1) c2->(r+8,cc) c3->(r+8,cc+1)
    const int grp = lane >> 2;
    #pragma unroll
    for (int mi = 0; mi < 4; mi++){
        #pragma unroll
        for (int ni = 0; ni < 8; ni++){
            const int r  = m0 + wm0 + mi*16 + grp;
            const int cc = n0 + wn0 + ni*8 + qd*2;
            float v0 = c[mi][ni][0], v1 = c[mi][ni][1];
            float v2 = c[mi][ni][2], v3 = c[mi][ni][3];
            if (bias_mode == 1){
                const float b0 = bias[cc], b1 = bias[cc+1];
                v0 += b0; v1 += b1; v2 += b0; v3 += b1;
            } else if (bias_mode == 2){
                const float b0 = bias[r], b1 = bias[r+8];
                v0 += b0; v1 += b0; v2 += b1; v3 += b1;
            }
            if (OH){
                __half* C = (__half*)C_ + (size_t)z*sC;
                *(__half2*)&C[(size_t)r     * ldc + cc] = __floats2half2_rn(v0, v1);
                *(__half2*)&C[(size_t)(r+8) * ldc + cc] = __floats2half2_rn(v2, v3);
            } else {
                float* C = (float*)C_ + (size_t)z*sC;
                *(float2*)&C[(size_t)r     * ldc + cc] = make_float2(v0, v1);
                *(float2*)&C[(size_t)(r+8) * ldc + cc] = make_float2(v2, v3);
            }
        }
    }
}

// fp32 -> fp16 elementwise (n multiple of 4)
__global__ void __launch_bounds__(256) f2h_k(const float* __restrict__ src,
                                             __half* __restrict__ dst, int n4)
{
    const int i = blockIdx.x * 256 + threadIdx.x;
    if (i < n4){
        float4 v = ((const float4*)src)[i];
        ((__half2*)dst)[2*i  ] = __floats2half2_rn(v.x, v.y);
        ((__half2*)dst)[2*i+1] = __floats2half2_rn(v.z, v.w);
    }
}

// Row softmax over SEQ=4096 fp16 in/out, scale folded in, fp32 math (exp2 form).
__global__ void __launch_bounds__(256) softmax_h(__half* __restrict__ S)
{
    __shared__ float red[8];
    __half* p = S + (size_t)blockIdx.x * SEQ;
    const int tid = threadIdx.x;
    const int lane = tid & 31, wid = tid >> 5;
    const float s2 = 0.03125f * 1.4426950408889634f;   // scale * log2(e)

    uint4 u[2];
    u[0] = ((const uint4*)p)[tid];
    u[1] = ((const uint4*)p)[tid + 256];

    float f[16];
    {
        const unsigned* w = (const unsigned*)u;
        #pragma unroll
        for (int i = 0; i < 8; i++){
            float2 t = h2f2(w[i]);
            f[2*i]   = t.x * s2;
            f[2*i+1] = t.y * s2;
        }
    }

    float mx = -1e30f;
    #pragma unroll
    for (int i = 0; i < 16; i++) mx = fmaxf(mx, f[i]);
    #pragma unroll
    for (int o = 16; o; o >>= 1) mx = fmaxf(mx, __shfl_xor_sync(0xffffffffu, mx, o));
    if (lane == 0) red[wid] = mx;
    __syncthreads();
    mx = red[0];
    #pragma unroll
    for (int w = 1; w < 8; w++) mx = fmaxf(mx, red[w]);
    __syncthreads();

    float sum = 0.f;
    #pragma unroll
    for (int i = 0; i < 16; i++){ f[i] = exp2f(f[i] - mx); sum += f[i]; }
    #pragma unroll
    for (int o = 16; o; o >>= 1) sum += __shfl_xor_sync(0xffffffffu, sum, o);
    if (lane == 0) red[wid] = sum;
    __syncthreads();
    sum = red[0];
    #pragma unroll
    for (int w = 1; w < 8; w++) sum += red[w];
    const float inv = 1.0f / sum;

    {
        unsigned* w = (unsigned*)u;
        #pragma unroll
        for (int i = 0; i < 8; i++) w[i] = packh2(f[2*i]*inv, f[2*i+1]*inv);
    }
    ((uint4*)p)[tid]       = u[0];
    ((uint4*)p)[tid + 256] = u[1];
}

extern "C" void kernel_launch(void* const* d_in, const int* in_sizes, int n_in,
                              void* d_out, int out_size)
{
    (void)in_sizes; (void)n_in; (void)out_size;
    const float* X  = (const float*)d_in[0];
    const float* Wq = (const float*)d_in[1];
    const float* bq = (const float*)d_in[2];
    const float* Wk = (const float*)d_in[3];
    const float* bk = (const float*)d_in[4];
    const float* Wv = (const float*)d_in[5];
    const float* bv = (const float*)d_in[6];
    float* out = (float*)d_out;

    __half *xh, *wqh, *wkh, *wvh, *qh, *kh, *vth, *sh;
    cudaGetSymbolAddress((void**)&xh,  g_xh);
    cudaGetSymbolAddress((void**)&wqh, g_wqh);
    cudaGetSymbolAddress((void**)&wkh, g_wkh);
    cudaGetSymbolAddress((void**)&wvh, g_wvh);
    cudaGetSymbolAddress((void**)&qh,  g_qh);
    cudaGetSymbolAddress((void**)&kh,  g_kh);
    cudaGetSymbolAddress((void**)&vth, g_vth);
    cudaGetSymbolAddress((void**)&sh,  g_sh);

    const int SMEM = NSTG * (BM + BN) * SROWW * 4;   // 165888 B
    cudaFuncSetAttribute(gemm_h2<true >, cudaFuncAttributeMaxDynamicSharedMemorySize, SMEM);
    cudaFuncSetAttribute(gemm_h2<false>, cudaFuncAttributeMaxDynamicSharedMemorySize, SMEM);

    // convert inputs to fp16
    f2h_k<<<(NROWS*EMB/4 + 255)/256, 256>>>(X,  xh,  NROWS*EMB/4);
    f2h_k<<<(EMB*EMB/4 + 255)/256, 256>>>(Wq, wqh, EMB*EMB/4);
    f2h_k<<<(EMB*EMB/4 + 255)/256, 256>>>(Wk, wkh, EMB*EMB/4);
    f2h_k<<<(EMB*EMB/4 + 255)/256, 256>>>(Wv, wvh, EMB*EMB/4);

    dim3 blk(256, 1, 1);

    // 1) q = X @ Wq^T + bq  -> fp16
    gemm_h2<true><<<dim3(EMB/BN, NROWS/BM, 1), blk, SMEM>>>(
        xh, EMB, 0, wqh, EMB, 0, bq, 1, qh, EMB, 0, EMB, 0);
    // 2) k = X @ Wk^T + bk
    gemm_h2<true><<<dim3(EMB/BN, NROWS/BM, 1), blk, SMEM>>>(
        xh, EMB, 0, wkh, EMB, 0, bk, 1, kh, EMB, 0, EMB, 0);
    // 3) Vt = Wv @ X^T + bv(row) -> fp16 [EMB, NROWS]
    gemm_h2<true><<<dim3(NROWS/BN, EMB/BM, 1), blk, SMEM>>>(
        wvh, EMB, 0, xh, EMB, 0, bv, 2, vth, NROWS, 0, EMB, 0);
    // 4) S[b] = q[b] @ k[b]^T -> fp16 (scale folded into softmax)
    gemm_h2<true><<<dim3(SEQ/BN, SEQ/BM, NB), blk, SMEM>>>(
        qh, EMB, (long long)SEQ*EMB, kh, EMB, (long long)SEQ*EMB, nullptr, 0,
        sh, SEQ, (long long)SEQ*SEQ, EMB, 0);
    // 5) softmax rows
    softmax_h<<<NROWS, 256>>>(sh);
    // 6) out[b] = P[b] @ Vt[:, b*S:(b+1)*S]^T -> fp32
    gemm_h2<false><<<dim3(EMB/BN, SEQ/BM, NB), blk, SMEM>>>(
        sh, SEQ, (long long)SEQ*SEQ, vth, NROWS, 0, nullptr, 0,
        out, EMB, (long long)SEQ*EMB, SEQ, SEQ);
}

// round 8
// speedup vs baseline: 1.0602x; 1.0602x over previous
#include <cuda_runtime.h>
#include <cuda_fp16.h>
#include <cstdint>

#define EMB   1024
#define NB    4
#define SEQ   4096
#define NROWS (NB*SEQ)   // 16384

#define BM    128        // CTA M tile
#define BN    256        // CTA N tile
#define BKH   64         // K halves per stage (4 x k16)
#define SROWW 36         // smem row stride in words; 36%32==4 -> conflict-free frags
#define NKS   4          // k16 steps per stage
#define NSTG  3          // pipeline stages

// fp16 scratch (device globals: allocation-free per harness rules)
__device__ __align__(1024) __half g_xh [(size_t)NROWS*EMB];
__device__ __align__(1024) __half g_wh [(size_t)3*EMB*EMB];    // Wq|Wk|Wv fp16
__device__ __align__(1024) float  g_bs [3*EMB];                // bq|bk|bv fp32
__device__ __align__(1024) __half g_qkh[(size_t)2*NROWS*EMB];  // q|k fp16
__device__ __align__(1024) __half g_vth[(size_t)NROWS*EMB];    // Vt[E, B*S]
__device__ __align__(1024) __half g_sh [(size_t)NB*SEQ*SEQ];   // scores / probs

__device__ __forceinline__ unsigned packh2(float x, float y){
    __half2 h = __floats2half2_rn(x, y);
    return *reinterpret_cast<unsigned*>(&h);
}
__device__ __forceinline__ float2 h2f2(unsigned u){
    __half2 h = *reinterpret_cast<__half2*>(&u);
    return __half22float2(h);
}
__device__ __forceinline__ uint32_t smem_u32(const void* p){
    uint32_t a;
    asm("{ .reg .u64 t; cvta.to.shared.u64 t, %1; cvt.u32.u64 %0, t; }" : "=r"(a) : "l"(p));
    return a;
}
__device__ __forceinline__ void cp16(uint32_t s, const void* g){
    asm volatile("cp.async.ca.shared.global [%0], [%1], 16;" :: "r"(s), "l"(g));
}
#define CP_COMMIT() asm volatile("cp.async.commit_group;" ::: "memory")
#define CP_WAIT(N)  asm volatile("cp.async.wait_group %0;" :: "n"(N) : "memory")

__device__ __forceinline__ void ldsm4(unsigned& r0, unsigned& r1, unsigned& r2, unsigned& r3,
                                      uint32_t addr){
    asm volatile("ldmatrix.sync.aligned.m8n8.x4.shared.b16 {%0,%1,%2,%3}, [%4];"
        : "=r"(r0), "=r"(r1), "=r"(r2), "=r"(r3) : "r"(addr));
}

__device__ __forceinline__ void mma16816(float c[4], const unsigned a[4],
                                         unsigned b0, unsigned b1){
    asm volatile(
        "mma.sync.aligned.m16n8k16.row.col.f32.f16.f16.f32 "
        "{%0,%1,%2,%3},{%4,%5,%6,%7},{%8,%9},{%0,%1,%2,%3};"
        : "+f"(c[0]), "+f"(c[1]), "+f"(c[2]), "+f"(c[3])
        : "r"(a[0]), "r"(a[1]), "r"(a[2]), "r"(a[3]), "r"(b0), "r"(b1));
}

// C[M,N] = A[M,K] * B[N,K]^T (+bias). All-fp16 inputs, K-major, fp32 accum.
// OH: output half (else float). bias_mode: 0 none, 1 col bias[n], 2 row bias[m].
// bstride: per-z offset into bias. bko: per-z offset into B's K dim (PV Vt slicing).
template<bool OH>
__global__ void __launch_bounds__(256,1) gemm_h2(
    const __half* __restrict__ A, int lda, long long sA,
    const __half* __restrict__ B, int ldb, long long sB,
    const float* __restrict__ bias, int bstride, int bias_mode,
    void* __restrict__ C_, int ldc, long long sC,
    int K, int bko)
{
    extern __shared__ __align__(16) unsigned sm[];
    const uint32_t sbase = smem_u32(sm);
    const uint32_t BOFFW = NSTG*BM*SROWW;   // B region word offset (after NSTG A stages)

    const int z  = blockIdx.z;
    const int m0 = blockIdx.y * BM;
    const int n0 = blockIdx.x * BN;
    const int tid  = threadIdx.x;
    const int lane = tid & 31;
    const int wid  = tid >> 5;
    const int qd   = lane & 3;             // 0..3
    const int wm0  = (wid >> 2) * 64;      // warp rows: 2 x 64
    const int wn0  = (wid & 3) * 64;       // warp cols: 4 x 64

    const __half* A0 = A + (size_t)z*sA + (size_t)m0*lda;
    const __half* B0 = B + (size_t)z*sB + (size_t)n0*ldb + (size_t)z*bko;
    const float*  bias_e = bias + (size_t)z*bstride;

    // ldmatrix per-lane byte addresses (stage-0 base; add stage/k offsets later)
    const uint32_t aAddr0 = sbase + (uint32_t)(((wm0 + (lane & 15))*SROWW) * 4) + ((lane >> 4) * 16);
    const uint32_t bAddr0 = sbase + (BOFFW + (uint32_t)(wn0 + ((lane >> 4) * 8) + (lane & 7))*SROWW) * 4
                          + (((lane >> 3) & 1) * 16);

    float c[4][8][4];
    #pragma unroll
    for (int mi = 0; mi < 4; mi++)
        #pragma unroll
        for (int ni = 0; ni < 8; ni++)
            #pragma unroll
            for (int j = 0; j < 4; j++) c[mi][ni][j] = 0.f;

    const int KT = K / BKH;

    auto issue = [&](int kt, int s){
        #pragma unroll
        for (int i = 0; i < 4; i++){                 // A: 128 rows x 8 chunks / 256 thr
            const int id = tid + 256*i;
            const int row = id >> 3, ch = id & 7;
            cp16(sbase + (s*BM*SROWW + row*SROWW + ch*4)*4,
                 A0 + (size_t)row*lda + kt*BKH + ch*8);
        }
        #pragma unroll
        for (int i = 0; i < 8; i++){                 // B: 256 rows x 8 chunks / 256 thr
            const int id = tid + 256*i;
            const int row = id >> 3, ch = id & 7;
            cp16(sbase + (BOFFW + s*BN*SROWW + row*SROWW + ch*4)*4,
                 B0 + (size_t)row*ldb + kt*BKH + ch*8);
        }
        CP_COMMIT();
    };

    issue(0, 0);
    issue(1, 1);

    int stg = 0;                       // kt % NSTG
    int stg2 = 2;                      // (kt+2) % NSTG
    for (int kt = 0; kt < KT; kt++){
        if (kt < KT-1) CP_WAIT(1); else CP_WAIT(0);
        __syncthreads();
        if (kt + 2 < KT) issue(kt + 2, stg2);

        const uint32_t aS = aAddr0 + (uint32_t)stg * (BM*SROWW*4);
        const uint32_t bS = bAddr0 + (uint32_t)stg * (BN*SROWW*4);

        #pragma unroll
        for (int ks = 0; ks < NKS; ks++){
            const uint32_t ko = (uint32_t)(ks * 32);   // 8 words per k16 step
            unsigned af[4][4];
            #pragma unroll
            for (int mi = 0; mi < 4; mi++)
                ldsm4(af[mi][0], af[mi][1], af[mi][2], af[mi][3],
                      aS + (uint32_t)(mi*16*SROWW*4) + ko);
            #pragma unroll
            for (int np = 0; np < 4; np++){            // ni pair (2*np, 2*np+1)
                unsigned b0, b1, b2, b3;
                ldsm4(b0, b1, b2, b3, bS + (uint32_t)(np*16*SROWW*4) + ko);
                #pragma unroll
                for (int mi = 0; mi < 4; mi++){
                    mma16816(c[mi][2*np  ], af[mi], b0, b1);
                    mma16816(c[mi][2*np+1], af[mi], b2, b3);
                }
            }
        }

        if (++stg  == NSTG) stg  = 0;
        if (++stg2 == NSTG) stg2 = 0;
    }

    // epilogue: c0->(r,cc) c1->(r,cc+1) c2->(r+8,cc) c3->(r+8,cc+1)
    const int grp = lane >> 2;
    #pragma unroll
    for (int mi = 0; mi < 4; mi++){
        #pragma unroll
        for (int ni = 0; ni < 8; ni++){
            const int r  = m0 + wm0 + mi*16 + grp;
            const int cc = n0 + wn0 + ni*8 + qd*2;
            float v0 = c[mi][ni][0], v1 = c[mi][ni][1];
            float v2 = c[mi][ni][2], v3 = c[mi][ni][3];
            if (bias_mode == 1){
                const float b0 = bias_e[cc], b1 = bias_e[cc+1];
                v0 += b0; v1 += b1; v2 += b0; v3 += b1;
            } else if (bias_mode == 2){
                const float b0 = bias_e[r], b1 = bias_e[r+8];
                v0 += b0; v1 += b0; v2 += b1; v3 += b1;
            }
            if (OH){
                __half* C = (__half*)C_ + (size_t)z*sC;
                *(__half2*)&C[(size_t)r     * ldc + cc] = __floats2half2_rn(v0, v1);
                *(__half2*)&C[(size_t)(r+8) * ldc + cc] = __floats2half2_rn(v2, v3);
            } else {
                float* C = (float*)C_ + (size_t)z*sC;
                *(float2*)&C[(size_t)r     * ldc + cc] = make_float2(v0, v1);
                *(float2*)&C[(size_t)(r+8) * ldc + cc] = make_float2(v2, v3);
            }
        }
    }
}

// One prep kernel: X->fp16, Wq/Wk/Wv->fp16 (contiguous), biases gathered (fp32).
// Blocks: [0,16384) X | [16384,19456) weights (1024 each) | [19456,19459) biases
__global__ void __launch_bounds__(256) prep_k(
    const float* __restrict__ X,
    const float* __restrict__ Wq, const float* __restrict__ Wk, const float* __restrict__ Wv,
    const float* __restrict__ bq, const float* __restrict__ bk, const float* __restrict__ bv,
    __half* __restrict__ xh, __half* __restrict__ wh, float* __restrict__ bs)
{
    const int b = blockIdx.x, t = threadIdx.x;
    if (b < NROWS*EMB/1024){                       // 16384 blocks for X
        const int i = b*256 + t;
        float4 v = ((const float4*)X)[i];
        ((__half2*)xh)[2*i  ] = __floats2half2_rn(v.x, v.y);
        ((__half2*)xh)[2*i+1] = __floats2half2_rn(v.z, v.w);
    } else if (b < NROWS*EMB/1024 + 3*EMB*EMB/1024){
        const int bb = b - NROWS*EMB/1024;
        const int wsel = bb >> 10;                 // 0..2
        const int i = (bb & 1023)*256 + t;
        const float* W = (wsel == 0) ? Wq : ((wsel == 1) ? Wk : Wv);
        float4 v = ((const float4*)W)[i];
        __half2* dst = (__half2*)(wh + (size_t)wsel*EMB*EMB);
        dst[2*i  ] = __floats2half2_rn(v.x, v.y);
        dst[2*i+1] = __floats2half2_rn(v.z, v.w);
    } else {
        const int s = b - (NROWS*EMB/1024 + 3*EMB*EMB/1024);   // 0..2
        const float* src = (s == 0) ? bq : ((s == 1) ? bk : bv);
        ((float4*)(bs + s*EMB))[t] = ((const float4*)src)[t];
    }
}

// Row softmax over SEQ=4096 fp16 in/out, scale folded in, fp32 math (exp2 form).
__global__ void __launch_bounds__(256) softmax_h(__half* __restrict__ S)
{
    __shared__ float red[8];
    __half* p = S + (size_t)blockIdx.x * SEQ;
    const int tid = threadIdx.x;
    const int lane = tid & 31, wid = tid >> 5;
    const float s2 = 0.03125f * 1.4426950408889634f;   // scale * log2(e)

    uint4 u[2];
    u[0] = ((const uint4*)p)[tid];
    u[1] = ((const uint4*)p)[tid + 256];

    float f[16];
    {
        const unsigned* w = (const unsigned*)u;
        #pragma unroll
        for (int i = 0; i < 8; i++){
            float2 t = h2f2(w[i]);
            f[2*i]   = t.x * s2;
            f[2*i+1] = t.y * s2;
        }
    }

    float mx = -1e30f;
    #pragma unroll
    for (int i = 0; i < 16; i++) mx = fmaxf(mx, f[i]);
    #pragma unroll
    for (int o = 16; o; o >>= 1) mx = fmaxf(mx, __shfl_xor_sync(0xffffffffu, mx, o));
    if (lane == 0) red[wid] = mx;
    __syncthreads();
    mx = red[0];
    #pragma unroll
    for (int w = 1; w < 8; w++) mx = fmaxf(mx, red[w]);
    __syncthreads();

    float sum = 0.f;
    #pragma unroll
    for (int i = 0; i < 16; i++){ f[i] = exp2f(f[i] - mx); sum += f[i]; }
    #pragma unroll
    for (int o = 16; o; o >>= 1) sum += __shfl_xor_sync(0xffffffffu, sum, o);
    if (lane == 0) red[wid] = sum;
    __syncthreads();
    sum = red[0];
    #pragma unroll
    for (int w = 1; w < 8; w++) sum += red[w];
    const float inv = 1.0f / sum;

    {
        unsigned* w = (unsigned*)u;
        #pragma unroll
        for (int i = 0; i < 8; i++) w[i] = packh2(f[2*i]*inv, f[2*i+1]*inv);
    }
    ((uint4*)p)[tid]       = u[0];
    ((uint4*)p)[tid + 256] = u[1];
}

extern "C" void kernel_launch(void* const* d_in, const int* in_sizes, int n_in,
                              void* d_out, int out_size)
{
    (void)in_sizes; (void)n_in; (void)out_size;
    const float* X  = (const float*)d_in[0];
    const float* Wq = (const float*)d_in[1];
    const float* bq = (const float*)d_in[2];
    const float* Wk = (const float*)d_in[3];
    const float* bk = (const float*)d_in[4];
    const float* Wv = (const float*)d_in[5];
    const float* bv = (const float*)d_in[6];
    float* out = (float*)d_out;

    __half *xh, *wh, *qkh, *vth, *sh;
    float  *bs;
    cudaGetSymbolAddress((void**)&xh,  g_xh);
    cudaGetSymbolAddress((void**)&wh,  g_wh);
    cudaGetSymbolAddress((void**)&bs,  g_bs);
    cudaGetSymbolAddress((void**)&qkh, g_qkh);
    cudaGetSymbolAddress((void**)&vth, g_vth);
    cudaGetSymbolAddress((void**)&sh,  g_sh);

    __half* qh = qkh;
    __half* kh = qkh + (size_t)NROWS*EMB;

    const int SMEM = NSTG * (BM + BN) * SROWW * 4;   // 165888 B
    cudaFuncSetAttribute(gemm_h2<true >, cudaFuncAttributeMaxDynamicSharedMemorySize, SMEM);
    cudaFuncSetAttribute(gemm_h2<false>, cudaFuncAttributeMaxDynamicSharedMemorySize, SMEM);

    dim3 blk(256, 1, 1);

    // 1) prep: convert X + weights to fp16, gather biases
    prep_k<<<NROWS*EMB/1024 + 3*EMB*EMB/1024 + 3, blk>>>(
        X, Wq, Wk, Wv, bq, bk, bv, xh, wh, bs);

    // 2) q,k = X @ {Wq,Wk}^T + {bq,bk}  (fused via z; 1024 CTAs)
    gemm_h2<true><<<dim3(EMB/BN, NROWS/BM, 2), blk, SMEM>>>(
        xh, EMB, 0, wh, EMB, (long long)EMB*EMB, bs, EMB, 1,
        qkh, EMB, (long long)NROWS*EMB, EMB, 0);

    // 3) Vt = Wv @ X^T + bv(row) -> fp16 [EMB, NROWS]
    gemm_h2<true><<<dim3(NROWS/BN, EMB/BM, 1), blk, SMEM>>>(
        wh + (size_t)2*EMB*EMB, EMB, 0, xh, EMB, 0, bs + 2*EMB, 0, 2,
        vth, NROWS, 0, EMB, 0);

    // 4) S[b] = q[b] @ k[b]^T -> fp16 (scale folded into softmax)
    gemm_h2<true><<<dim3(SEQ/BN, SEQ/BM, NB), blk, SMEM>>>(
        qh, EMB, (long long)SEQ*EMB, kh, EMB, (long long)SEQ*EMB, nullptr, 0, 0,
        sh, SEQ, (long long)SEQ*SEQ, EMB, 0);

    // 5) softmax rows
    softmax_h<<<NROWS, blk>>>(sh);

    // 6) out[b] = P[b] @ Vt[:, b*S:(b+1)*S]^T -> fp32
    gemm_h2<false><<<dim3(EMB/BN, SEQ/BM, NB), blk, SMEM>>>(
        sh, SEQ, (long long)SEQ*SEQ, vth, NROWS, 0, nullptr, 0, 0,
        out, EMB, (long long)SEQ*EMB, SEQ, SEQ);
}

// round 9
// speedup vs baseline: 1.0623x; 1.0020x over previous
#include <cuda_runtime.h>
#include <cuda_fp16.h>
#include <cstdint>

#define EMB   1024
#define NB    4
#define SEQ   4096
#define NROWS (NB*SEQ)   // 16384

#define BM    128        // CTA M tile
#define BN    256        // CTA N tile
#define BKH   64         // K halves per stage (4 x k16)
#define SROWW 36         // smem row stride in words; 36%32==4 -> conflict-free frags
#define NKS   4          // k16 steps per stage
#define NSTG  3          // pipeline stages

// fp16 scratch (device globals: allocation-free per harness rules)
__device__ __align__(1024) __half g_xh [(size_t)NROWS*EMB];
__device__ __align__(1024) __half g_wh [(size_t)3*EMB*EMB];    // Wq|Wk|Wv fp16
__device__ __align__(1024) float  g_bs [3*EMB];                // bq|bk|bv fp32
__device__ __align__(1024) __half g_qkh[(size_t)2*NROWS*EMB];  // q|k fp16
__device__ __align__(1024) __half g_vth[(size_t)NROWS*EMB];    // Vt[E, B*S]
__device__ __align__(1024) __half g_sh [(size_t)NB*SEQ*SEQ];   // scores / probs

__device__ __forceinline__ unsigned packh2(float x, float y){
    __half2 h = __floats2half2_rn(x, y);
    return *reinterpret_cast<unsigned*>(&h);
}
__device__ __forceinline__ float2 h2f2(unsigned u){
    __half2 h = *reinterpret_cast<__half2*>(&u);
    return __half22float2(h);
}
__device__ __forceinline__ uint32_t smem_u32(const void* p){
    uint32_t a;
    asm("{ .reg .u64 t; cvta.to.shared.u64 t, %1; cvt.u32.u64 %0, t; }" : "=r"(a) : "l"(p));
    return a;
}
__device__ __forceinline__ void cp16(uint32_t s, const void* g){
    asm volatile("cp.async.ca.shared.global [%0], [%1], 16;" :: "r"(s), "l"(g));
}
#define CP_COMMIT() asm volatile("cp.async.commit_group;" ::: "memory")
#define CP_WAIT(N)  asm volatile("cp.async.wait_group %0;" :: "n"(N) : "memory")

__device__ __forceinline__ void ldsm4(unsigned& r0, unsigned& r1, unsigned& r2, unsigned& r3,
                                      uint32_t addr){
    asm volatile("ldmatrix.sync.aligned.m8n8.x4.shared.b16 {%0,%1,%2,%3}, [%4];"
        : "=r"(r0), "=r"(r1), "=r"(r2), "=r"(r3) : "r"(addr));
}

__device__ __forceinline__ void mma16816(float c[4], const unsigned a[4],
                                         unsigned b0, unsigned b1){
    asm volatile(
        "mma.sync.aligned.m16n8k16.row.col.f32.f16.f16.f32 "
        "{%0,%1,%2,%3},{%4,%5,%6,%7},{%8,%9},{%0,%1,%2,%3};"
        : "+f"(c[0]), "+f"(c[1]), "+f"(c[2]), "+f"(c[3])
        : "r"(a[0]), "r"(a[1]), "r"(a[2]), "r"(a[3]), "r"(b0), "r"(b1));
}

// C[M,N] = A[M,K] * B[N,K]^T (+bias). All-fp16 inputs, K-major, fp32 accum.
// OH: output half (else float). bias_mode: 0 none, 1 col bias[n], 2 row bias[m].
// bstride: per-z offset into bias. bko: per-z offset into B's K dim (PV Vt slicing).
template<bool OH>
__global__ void __launch_bounds__(256,1) gemm_h2(
    const __half* __restrict__ A, int lda, long long sA,
    const __half* __restrict__ B, int ldb, long long sB,
    const float* __restrict__ bias, int bstride, int bias_mode,
    void* __restrict__ C_, int ldc, long long sC,
    int K, int bko)
{
    extern __shared__ __align__(16) unsigned sm[];
    const uint32_t sbase = smem_u32(sm);
    const uint32_t BOFFW = NSTG*BM*SROWW;   // B region word offset (after NSTG A stages)

    const int z  = blockIdx.z;
    const int m0 = blockIdx.y * BM;
    const int n0 = blockIdx.x * BN;
    const int tid  = threadIdx.x;
    const int lane = tid & 31;
    const int wid  = tid >> 5;
    const int qd   = lane & 3;             // 0..3
    const int wm0  = (wid >> 2) * 64;      // warp rows: 2 x 64
    const int wn0  = (wid & 3) * 64;       // warp cols: 4 x 64

    const __half* A0 = A + (size_t)z*sA + (size_t)m0*lda;
    const __half* B0 = B + (size_t)z*sB + (size_t)n0*ldb + (size_t)z*bko;
    const float*  bias_e = bias + (size_t)z*bstride;

    // ldmatrix per-lane byte addresses (stage-0 base; add stage/k offsets later)
    const uint32_t aAddr0 = sbase + (uint32_t)(((wm0 + (lane & 15))*SROWW) * 4) + ((lane >> 4) * 16);
    const uint32_t bAddr0 = sbase + (BOFFW + (uint32_t)(wn0 + ((lane >> 4) * 8) + (lane & 7))*SROWW) * 4
                          + (((lane >> 3) & 1) * 16);

    float c[4][8][4];
    #pragma unroll
    for (int mi = 0; mi < 4; mi++)
        #pragma unroll
        for (int ni = 0; ni < 8; ni++)
            #pragma unroll
            for (int j = 0; j < 4; j++) c[mi][ni][j] = 0.f;

    const int KT = K / BKH;

    auto issue = [&](int kt, int s){
        #pragma unroll
        for (int i = 0; i < 4; i++){                 // A: 128 rows x 8 chunks / 256 thr
            const int id = tid + 256*i;
            const int row = id >> 3, ch = id & 7;
            cp16(sbase + (s*BM*SROWW + row*SROWW + ch*4)*4,
                 A0 + (size_t)row*lda + kt*BKH + ch*8);
        }
        #pragma unroll
        for (int i = 0; i < 8; i++){                 // B: 256 rows x 8 chunks / 256 thr
            const int id = tid + 256*i;
            const int row = id >> 3, ch = id & 7;
            cp16(sbase + (BOFFW + s*BN*SROWW + row*SROWW + ch*4)*4,
                 B0 + (size_t)row*ldb + kt*BKH + ch*8);
        }
        CP_COMMIT();
    };

    issue(0, 0);
    issue(1, 1);

    int stg = 0;                       // kt % NSTG
    int stg2 = 2;                      // (kt+2) % NSTG
    for (int kt = 0; kt < KT; kt++){
        if (kt < KT-1) CP_WAIT(1); else CP_WAIT(0);
        __syncthreads();
        if (kt + 2 < KT) issue(kt + 2, stg2);

        const uint32_t aS = aAddr0 + (uint32_t)stg * (BM*SROWW*4);
        const uint32_t bS = bAddr0 + (uint32_t)stg * (BN*SROWW*4);

        #pragma unroll
        for (int ks = 0; ks < NKS; ks++){
            const uint32_t ko = (uint32_t)(ks * 32);   // 8 words per k16 step
            unsigned af[4][4];
            #pragma unroll
            for (int mi = 0; mi < 4; mi++)
                ldsm4(af[mi][0], af[mi][1], af[mi][2], af[mi][3],
                      aS + (uint32_t)(mi*16*SROWW*4) + ko);
            #pragma unroll
            for (int np = 0; np < 4; np++){            // ni pair (2*np, 2*np+1)
                unsigned b0, b1, b2, b3;
                ldsm4(b0, b1, b2, b3, bS + (uint32_t)(np*16*SROWW*4) + ko);
                #pragma unroll
                for (int mi = 0; mi < 4; mi++){
                    mma16816(c[mi][2*np  ], af[mi], b0, b1);
                    mma16816(c[mi][2*np+1], af[mi], b2, b3);
                }
            }
        }

        if (++stg  == NSTG) stg  = 0;
        if (++stg2 == NSTG) stg2 = 0;
    }

    // epilogue: c0->(r,cc) c1->(r,cc+1) c2->(r+8,cc) c3->(r+8,cc+1)
    const int grp = lane >> 2;
    #pragma unroll
    for (int mi = 0; mi < 4; mi++){
        #pragma unroll
        for (int ni = 0; ni < 8; ni++){
            const int r  = m0 + wm0 + mi*16 + grp;
            const int cc = n0 + wn0 + ni*8 + qd*2;
            float v0 = c[mi][ni][0], v1 = c[mi][ni][1];
            float v2 = c[mi][ni][2], v3 = c[mi][ni][3];
            if (bias_mode == 1){
                const float b0 = bias_e[cc], b1 = bias_e[cc+1];
                v0 += b0; v1 += b1; v2 += b0; v3 += b1;
            } else if (bias_mode == 2){
                const float b0 = bias_e[r], b1 = bias_e[r+8];
                v0 += b0; v1 += b0; v2 += b1; v3 += b1;
            }
            if (OH){
                __half* C = (__half*)C_ + (size_t)z*sC;
                *(__half2*)&C[(size_t)r     * ldc + cc] = __floats2half2_rn(v0, v1);
                *(__half2*)&C[(size_t)(r+8) * ldc + cc] = __floats2half2_rn(v2, v3);
            } else {
                float* C = (float*)C_ + (size_t)z*sC;
                *(float2*)&C[(size_t)r     * ldc + cc] = make_float2(v0, v1);
                *(float2*)&C[(size_t)(r+8) * ldc + cc] = make_float2(v2, v3);
            }
        }
    }
}

// One prep kernel: X->fp16, Wq/Wk/Wv->fp16 (contiguous), biases gathered (fp32).
// Blocks: [0,16384) X | [16384,19456) weights (1024 each) | [19456,19459) biases
__global__ void __launch_bounds__(256) prep_k(
    const float* __restrict__ X,
    const float* __restrict__ Wq, const float* __restrict__ Wk, const float* __restrict__ Wv,
    const float* __restrict__ bq, const float* __restrict__ bk, const float* __restrict__ bv,
    __half* __restrict__ xh, __half* __restrict__ wh, float* __restrict__ bs)
{
    const int b = blockIdx.x, t = threadIdx.x;
    if (b < NROWS*EMB/1024){                       // 16384 blocks for X
        const int i = b*256 + t;
        float4 v = ((const float4*)X)[i];
        ((__half2*)xh)[2*i  ] = __floats2half2_rn(v.x, v.y);
        ((__half2*)xh)[2*i+1] = __floats2half2_rn(v.z, v.w);
    } else if (b < NROWS*EMB/1024 + 3*EMB*EMB/1024){
        const int bb = b - NROWS*EMB/1024;
        const int wsel = bb >> 10;                 // 0..2
        const int i = (bb & 1023)*256 + t;
        const float* W = (wsel == 0) ? Wq : ((wsel == 1) ? Wk : Wv);
        float4 v = ((const float4*)W)[i];
        __half2* dst = (__half2*)(wh + (size_t)wsel*EMB*EMB);
        dst[2*i  ] = __floats2half2_rn(v.x, v.y);
        dst[2*i+1] = __floats2half2_rn(v.z, v.w);
    } else {
        const int s = b - (NROWS*EMB/1024 + 3*EMB*EMB/1024);   // 0..2
        const float* src = (s == 0) ? bq : ((s == 1) ? bk : bv);
        ((float4*)(bs + s*EMB))[t] = ((const float4*)src)[t];
    }
}

// Row softmax over SEQ=4096 fp16 in/out, scale folded in, fp32 math (exp2 form).
__global__ void __launch_bounds__(256) softmax_h(__half* __restrict__ S)
{
    __shared__ float red[8];
    __half* p = S + (size_t)blockIdx.x * SEQ;
    const int tid = threadIdx.x;
    const int lane = tid & 31, wid = tid >> 5;
    const float s2 = 0.03125f * 1.4426950408889634f;   // scale * log2(e)

    uint4 u[2];
    u[0] = ((const uint4*)p)[tid];
    u[1] = ((const uint4*)p)[tid + 256];

    float f[16];
    {
        const unsigned* w = (const unsigned*)u;
        #pragma unroll
        for (int i = 0; i < 8; i++){
            float2 t = h2f2(w[i]);
            f[2*i]   = t.x * s2;
            f[2*i+1] = t.y * s2;
        }
    }

    float mx = -1e30f;
    #pragma unroll
    for (int i = 0; i < 16; i++) mx = fmaxf(mx, f[i]);
    #pragma unroll
    for (int o = 16; o; o >>= 1) mx = fmaxf(mx, __shfl_xor_sync(0xffffffffu, mx, o));
    if (lane == 0) red[wid] = mx;
    __syncthreads();
    mx = red[0];
    #pragma unroll
    for (int w = 1; w < 8; w++) mx = fmaxf(mx, red[w]);
    __syncthreads();

    float sum = 0.f;
    #pragma unroll
    for (int i = 0; i < 16; i++){ f[i] = exp2f(f[i] - mx); sum += f[i]; }
    #pragma unroll
    for (int o = 16; o; o >>= 1) sum += __shfl_xor_sync(0xffffffffu, sum, o);
    if (lane == 0) red[wid] = sum;
    __syncthreads();
    sum = red[0];
    #pragma unroll
    for (int w = 1; w < 8; w++) sum += red[w];
    const float inv = 1.0f / sum;

    {
        unsigned* w = (unsigned*)u;
        #pragma unroll
        for (int i = 0; i < 8; i++) w[i] = packh2(f[2*i]*inv, f[2*i+1]*inv);
    }
    ((uint4*)p)[tid]       = u[0];
    ((uint4*)p)[tid + 256] = u[1];
}

extern "C" void kernel_launch(void* const* d_in, const int* in_sizes, int n_in,
                              void* d_out, int out_size)
{
    (void)in_sizes; (void)n_in; (void)out_size;
    const float* X  = (const float*)d_in[0];
    const float* Wq = (const float*)d_in[1];
    const float* bq = (const float*)d_in[2];
    const float* Wk = (const float*)d_in[3];
    const float* bk = (const float*)d_in[4];
    const float* Wv = (const float*)d_in[5];
    const float* bv = (const float*)d_in[6];
    float* out = (float*)d_out;

    __half *xh, *wh, *qkh, *vth, *sh;
    float  *bs;
    cudaGetSymbolAddress((void**)&xh,  g_xh);
    cudaGetSymbolAddress((void**)&wh,  g_wh);
    cudaGetSymbolAddress((void**)&bs,  g_bs);
    cudaGetSymbolAddress((void**)&qkh, g_qkh);
    cudaGetSymbolAddress((void**)&vth, g_vth);
    cudaGetSymbolAddress((void**)&sh,  g_sh);

    __half* qh = qkh;
    __half* kh = qkh + (size_t)NROWS*EMB;

    const int SMEM = NSTG * (BM + BN) * SROWW * 4;   // 165888 B
    cudaFuncSetAttribute(gemm_h2<true >, cudaFuncAttributeMaxDynamicSharedMemorySize, SMEM);
    cudaFuncSetAttribute(gemm_h2<false>, cudaFuncAttributeMaxDynamicSharedMemorySize, SMEM);

    dim3 blk(256, 1, 1);

    // 1) prep: convert X + weights to fp16, gather biases
    prep_k<<<NROWS*EMB/1024 + 3*EMB*EMB/1024 + 3, blk>>>(
        X, Wq, Wk, Wv, bq, bk, bv, xh, wh, bs);

    // 2) q,k = X @ {Wq,Wk}^T + {bq,bk}  (fused via z; 1024 CTAs)
    gemm_h2<true><<<dim3(EMB/BN, NROWS/BM, 2), blk, SMEM>>>(
        xh, EMB, 0, wh, EMB, (long long)EMB*EMB, bs, EMB, 1,
        qkh, EMB, (long long)NROWS*EMB, EMB, 0);

    // 3) Vt = Wv @ X^T + bv(row) -> fp16 [EMB, NROWS]
    gemm_h2<true><<<dim3(NROWS/BN, EMB/BM, 1), blk, SMEM>>>(
        wh + (size_t)2*EMB*EMB, EMB, 0, xh, EMB, 0, bs + 2*EMB, 0, 2,
        vth, NROWS, 0, EMB, 0);

    // 4) S[b] = q[b] @ k[b]^T -> fp16 (scale folded into softmax)
    gemm_h2<true><<<dim3(SEQ/BN, SEQ/BM, NB), blk, SMEM>>>(
        qh, EMB, (long long)SEQ*EMB, kh, EMB, (long long)SEQ*EMB, nullptr, 0, 0,
        sh, SEQ, (long long)SEQ*SEQ, EMB, 0);

    // 5) softmax rows
    softmax_h<<<NROWS, blk>>>(sh);

    // 6) out[b] = P[b] @ Vt[:, b*S:(b+1)*S]^T -> fp32
    gemm_h2<false><<<dim3(EMB/BN, SEQ/BM, NB), blk, SMEM>>>(
        sh, SEQ, (long long)SEQ*SEQ, vth, NROWS, 0, nullptr, 0, 0,
        out, EMB, (long long)SEQ*EMB, SEQ, SEQ);
}

// round 10
// speedup vs baseline: 1.0638x; 1.0014x over previous
#include <cuda_runtime.h>
#include <cuda_fp16.h>
#include <cstdint>

#define EMB   1024
#define NB    4
#define SEQ   4096
#define NROWS (NB*SEQ)   // 16384

#define BM    128        // CTA M tile
#define BN    256        // CTA N tile
#define BKH   64         // K halves per stage (4 x k16)
#define SROWW 36         // smem row stride in words; 36%32==4 -> conflict-free frags
#define NKS   4          // k16 steps per stage
#define NSTG  3          // pipeline stages

// fp16 scratch (device globals: allocation-free per harness rules)
__device__ __align__(1024) __half g_xh [(size_t)NROWS*EMB];
__device__ __align__(1024) __half g_wh [(size_t)3*EMB*EMB];    // Wq|Wk|Wv fp16
__device__ __align__(1024) float  g_bs [3*EMB];                // bq|bk|bv fp32
__device__ __align__(1024) __half g_qkh[(size_t)2*NROWS*EMB];  // q|k fp16
__device__ __align__(1024) __half g_vth[(size_t)NROWS*EMB];    // Vt[E, B*S]
__device__ __align__(1024) __half g_sh [(size_t)NB*SEQ*SEQ];   // scores / probs

__device__ __forceinline__ unsigned packh2(float x, float y){
    __half2 h = __floats2half2_rn(x, y);
    return *reinterpret_cast<unsigned*>(&h);
}
__device__ __forceinline__ float2 h2f2(unsigned u){
    __half2 h = *reinterpret_cast<__half2*>(&u);
    return __half22float2(h);
}
__device__ __forceinline__ uint32_t smem_u32(const void* p){
    uint32_t a;
    asm("{ .reg .u64 t; cvta.to.shared.u64 t, %1; cvt.u32.u64 %0, t; }" : "=r"(a) : "l"(p));
    return a;
}
__device__ __forceinline__ void cp16(uint32_t s, const void* g){
    asm volatile("cp.async.ca.shared.global [%0], [%1], 16;" :: "r"(s), "l"(g));
}
#define CP_COMMIT() asm volatile("cp.async.commit_group;" ::: "memory")
#define CP_WAIT(N)  asm volatile("cp.async.wait_group %0;" :: "n"(N) : "memory")

__device__ __forceinline__ void ldsm4(unsigned& r0, unsigned& r1, unsigned& r2, unsigned& r3,
                                      uint32_t addr){
    asm volatile("ldmatrix.sync.aligned.m8n8.x4.shared.b16 {%0,%1,%2,%3}, [%4];"
        : "=r"(r0), "=r"(r1), "=r"(r2), "=r"(r3) : "r"(addr));
}

__device__ __forceinline__ void mma16816(float c[4], const unsigned a[4],
                                         unsigned b0, unsigned b1){
    asm volatile(
        "mma.sync.aligned.m16n8k16.row.col.f32.f16.f16.f32 "
        "{%0,%1,%2,%3},{%4,%5,%6,%7},{%8,%9},{%0,%1,%2,%3};"
        : "+f"(c[0]), "+f"(c[1]), "+f"(c[2]), "+f"(c[3])
        : "r"(a[0]), "r"(a[1]), "r"(a[2]), "r"(a[3]), "r"(b0), "r"(b1));
}

// C[M,N] = A[M,K] * B[N,K]^T (+bias). All-fp16 inputs, K-major, fp32 accum.
// OH: output half (else float). bias_mode: 0 none, 1 col bias[n], 2 row bias[m].
// bstride: per-z offset into bias. bko: per-z offset into B's K dim (PV Vt slicing).
template<bool OH>
__global__ void __launch_bounds__(256,1) gemm_h2(
    const __half* __restrict__ A, int lda, long long sA,
    const __half* __restrict__ B, int ldb, long long sB,
    const float* __restrict__ bias, int bstride, int bias_mode,
    void* __restrict__ C_, int ldc, long long sC,
    int K, int bko)
{
    extern __shared__ __align__(16) unsigned sm[];
    const uint32_t sbase = smem_u32(sm);
    const uint32_t BOFFW = NSTG*BM*SROWW;   // B region word offset (after NSTG A stages)

    const int z  = blockIdx.z;
    const int m0 = blockIdx.y * BM;
    const int n0 = blockIdx.x * BN;
    const int tid  = threadIdx.x;
    const int lane = tid & 31;
    const int wid  = tid >> 5;
    const int qd   = lane & 3;             // 0..3
    const int wm0  = (wid >> 2) * 64;      // warp rows: 2 x 64
    const int wn0  = (wid & 3) * 64;       // warp cols: 4 x 64

    const __half* A0 = A + (size_t)z*sA + (size_t)m0*lda;
    const __half* B0 = B + (size_t)z*sB + (size_t)n0*ldb + (size_t)z*bko;
    const float*  bias_e = bias + (size_t)z*bstride;

    // ldmatrix per-lane byte addresses (stage-0 base; add stage/k offsets later)
    const uint32_t aAddr0 = sbase + (uint32_t)(((wm0 + (lane & 15))*SROWW) * 4) + ((lane >> 4) * 16);
    const uint32_t bAddr0 = sbase + (BOFFW + (uint32_t)(wn0 + ((lane >> 4) * 8) + (lane & 7))*SROWW) * 4
                          + (((lane >> 3) & 1) * 16);

    float c[4][8][4];
    #pragma unroll
    for (int mi = 0; mi < 4; mi++)
        #pragma unroll
        for (int ni = 0; ni < 8; ni++)
            #pragma unroll
            for (int j = 0; j < 4; j++) c[mi][ni][j] = 0.f;

    const int KT = K / BKH;

    auto issue = [&](int kt, int s){
        #pragma unroll
        for (int i = 0; i < 4; i++){                 // A: 128 rows x 8 chunks / 256 thr
            const int id = tid + 256*i;
            const int row = id >> 3, ch = id & 7;
            cp16(sbase + (s*BM*SROWW + row*SROWW + ch*4)*4,
                 A0 + (size_t)row*lda + kt*BKH + ch*8);
        }
        #pragma unroll
        for (int i = 0; i < 8; i++){                 // B: 256 rows x 8 chunks / 256 thr
            const int id = tid + 256*i;
            const int row = id >> 3, ch = id & 7;
            cp16(sbase + (BOFFW + s*BN*SROWW + row*SROWW + ch*4)*4,
                 B0 + (size_t)row*ldb + kt*BKH + ch*8);
        }
        CP_COMMIT();
    };

    issue(0, 0);
    issue(1, 1);

    int stg = 0;                       // kt % NSTG
    int stg2 = 2;                      // (kt+2) % NSTG
    for (int kt = 0; kt < KT; kt++){
        if (kt < KT-1) CP_WAIT(1); else CP_WAIT(0);
        __syncthreads();
        if (kt + 2 < KT) issue(kt + 2, stg2);

        const uint32_t aS = aAddr0 + (uint32_t)stg * (BM*SROWW*4);
        const uint32_t bS = bAddr0 + (uint32_t)stg * (BN*SROWW*4);

        #pragma unroll
        for (int ks = 0; ks < NKS; ks++){
            const uint32_t ko = (uint32_t)(ks * 32);   // 8 words per k16 step
            unsigned af[4][4];
            #pragma unroll
            for (int mi = 0; mi < 4; mi++)
                ldsm4(af[mi][0], af[mi][1], af[mi][2], af[mi][3],
                      aS + (uint32_t)(mi*16*SROWW*4) + ko);
            #pragma unroll
            for (int np = 0; np < 4; np++){            // ni pair (2*np, 2*np+1)
                unsigned b0, b1, b2, b3;
                ldsm4(b0, b1, b2, b3, bS + (uint32_t)(np*16*SROWW*4) + ko);
                #pragma unroll
                for (int mi = 0; mi < 4; mi++){
                    mma16816(c[mi][2*np  ], af[mi], b0, b1);
                    mma16816(c[mi][2*np+1], af[mi], b2, b3);
                }
            }
        }

        if (++stg  == NSTG) stg  = 0;
        if (++stg2 == NSTG) stg2 = 0;
    }

    // epilogue: c0->(r,cc) c1->(r,cc+1) c2->(r+8,cc) c3->(r+8,cc+1)
    const int grp = lane >> 2;
    #pragma unroll
    for (int mi = 0; mi < 4; mi++){
        #pragma unroll
        for (int ni = 0; ni < 8; ni++){
            const int r  = m0 + wm0 + mi*16 + grp;
            const int cc = n0 + wn0 + ni*8 + qd*2;
            float v0 = c[mi][ni][0], v1 = c[mi][ni][1];
            float v2 = c[mi][ni][2], v3 = c[mi][ni][3];
            if (bias_mode == 1){
                const float b0 = bias_e[cc], b1 = bias_e[cc+1];
                v0 += b0; v1 += b1; v2 += b0; v3 += b1;
            } else if (bias_mode == 2){
                const float b0 = bias_e[r], b1 = bias_e[r+8];
                v0 += b0; v1 += b0; v2 += b1; v3 += b1;
            }
            if (OH){
                __half* C = (__half*)C_ + (size_t)z*sC;
                *(__half2*)&C[(size_t)r     * ldc + cc] = __floats2half2_rn(v0, v1);
                *(__half2*)&C[(size_t)(r+8) * ldc + cc] = __floats2half2_rn(v2, v3);
            } else {
                float* C = (float*)C_ + (size_t)z*sC;
                *(float2*)&C[(size_t)r     * ldc + cc] = make_float2(v0, v1);
                *(float2*)&C[(size_t)(r+8) * ldc + cc] = make_float2(v2, v3);
            }
        }
    }
}

// One prep kernel: X->fp16, Wq/Wk/Wv->fp16 (contiguous), biases gathered (fp32).
// Blocks: [0,16384) X | [16384,19456) weights (1024 each) | [19456,19459) biases
__global__ void __launch_bounds__(256) prep_k(
    const float* __restrict__ X,
    const float* __restrict__ Wq, const float* __restrict__ Wk, const float* __restrict__ Wv,
    const float* __restrict__ bq, const float* __restrict__ bk, const float* __restrict__ bv,
    __half* __restrict__ xh, __half* __restrict__ wh, float* __restrict__ bs)
{
    const int b = blockIdx.x, t = threadIdx.x;
    if (b < NROWS*EMB/1024){                       // 16384 blocks for X
        const int i = b*256 + t;
        float4 v = ((const float4*)X)[i];
        ((__half2*)xh)[2*i  ] = __floats2half2_rn(v.x, v.y);
        ((__half2*)xh)[2*i+1] = __floats2half2_rn(v.z, v.w);
    } else if (b < NROWS*EMB/1024 + 3*EMB*EMB/1024){
        const int bb = b - NROWS*EMB/1024;
        const int wsel = bb >> 10;                 // 0..2
        const int i = (bb & 1023)*256 + t;
        const float* W = (wsel == 0) ? Wq : ((wsel == 1) ? Wk : Wv);
        float4 v = ((const float4*)W)[i];
        __half2* dst = (__half2*)(wh + (size_t)wsel*EMB*EMB);
        dst[2*i  ] = __floats2half2_rn(v.x, v.y);
        dst[2*i+1] = __floats2half2_rn(v.z, v.w);
    } else {
        const int s = b - (NROWS*EMB/1024 + 3*EMB*EMB/1024);   // 0..2
        const float* src = (s == 0) ? bq : ((s == 1) ? bk : bv);
        ((float4*)(bs + s*EMB))[t] = ((const float4*)src)[t];
    }
}

// Row softmax over SEQ=4096 fp16 in/out, scale folded in, fp32 math (exp2 form).
__global__ void __launch_bounds__(256) softmax_h(__half* __restrict__ S)
{
    __shared__ float red[8];
    __half* p = S + (size_t)blockIdx.x * SEQ;
    const int tid = threadIdx.x;
    const int lane = tid & 31, wid = tid >> 5;
    const float s2 = 0.03125f * 1.4426950408889634f;   // scale * log2(e)

    uint4 u[2];
    u[0] = ((const uint4*)p)[tid];
    u[1] = ((const uint4*)p)[tid + 256];

    float f[16];
    {
        const unsigned* w = (const unsigned*)u;
        #pragma unroll
        for (int i = 0; i < 8; i++){
            float2 t = h2f2(w[i]);
            f[2*i]   = t.x * s2;
            f[2*i+1] = t.y * s2;
        }
    }

    float mx = -1e30f;
    #pragma unroll
    for (int i = 0; i < 16; i++) mx = fmaxf(mx, f[i]);
    #pragma unroll
    for (int o = 16; o; o >>= 1) mx = fmaxf(mx, __shfl_xor_sync(0xffffffffu, mx, o));
    if (lane == 0) red[wid] = mx;
    __syncthreads();
    mx = red[0];
    #pragma unroll
    for (int w = 1; w < 8; w++) mx = fmaxf(mx, red[w]);
    __syncthreads();

    float sum = 0.f;
    #pragma unroll
    for (int i = 0; i < 16; i++){ f[i] = exp2f(f[i] - mx); sum += f[i]; }
    #pragma unroll
    for (int o = 16; o; o >>= 1) sum += __shfl_xor_sync(0xffffffffu, sum, o);
    if (lane == 0) red[wid] = sum;
    __syncthreads();
    sum = red[0];
    #pragma unroll
    for (int w = 1; w < 8; w++) sum += red[w];
    const float inv = 1.0f / sum;

    {
        unsigned* w = (unsigned*)u;
        #pragma unroll
        for (int i = 0; i < 8; i++) w[i] = packh2(f[2*i]*inv, f[2*i+1]*inv);
    }
    ((uint4*)p)[tid]       = u[0];
    ((uint4*)p)[tid + 256] = u[1];
}

extern "C" void kernel_launch(void* const* d_in, const int* in_sizes, int n_in,
                              void* d_out, int out_size)
{
    (void)in_sizes; (void)n_in; (void)out_size;
    const float* X  = (const float*)d_in[0];
    const float* Wq = (const float*)d_in[1];
    const float* bq = (const float*)d_in[2];
    const float* Wk = (const float*)d_in[3];
    const float* bk = (const float*)d_in[4];
    const float* Wv = (const float*)d_in[5];
    const float* bv = (const float*)d_in[6];
    float* out = (float*)d_out;

    __half *xh, *wh, *qkh, *vth, *sh;
    float  *bs;
    cudaGetSymbolAddress((void**)&xh,  g_xh);
    cudaGetSymbolAddress((void**)&wh,  g_wh);
    cudaGetSymbolAddress((void**)&bs,  g_bs);
    cudaGetSymbolAddress((void**)&qkh, g_qkh);
    cudaGetSymbolAddress((void**)&vth, g_vth);
    cudaGetSymbolAddress((void**)&sh,  g_sh);

    __half* qh = qkh;
    __half* kh = qkh + (size_t)NROWS*EMB;

    const int SMEM = NSTG * (BM + BN) * SROWW * 4;   // 165888 B
    cudaFuncSetAttribute(gemm_h2<true >, cudaFuncAttributeMaxDynamicSharedMemorySize, SMEM);
    cudaFuncSetAttribute(gemm_h2<false>, cudaFuncAttributeMaxDynamicSharedMemorySize, SMEM);

    dim3 blk(256, 1, 1);

    // 1) prep: convert X + weights to fp16, gather biases
    prep_k<<<NROWS*EMB/1024 + 3*EMB*EMB/1024 + 3, blk>>>(
        X, Wq, Wk, Wv, bq, bk, bv, xh, wh, bs);

    // 2) q,k = X @ {Wq,Wk}^T + {bq,bk}  (fused via z; 1024 CTAs)
    gemm_h2<true><<<dim3(EMB/BN, NROWS/BM, 2), blk, SMEM>>>(
        xh, EMB, 0, wh, EMB, (long long)EMB*EMB, bs, EMB, 1,
        qkh, EMB, (long long)NROWS*EMB, EMB, 0);

    // 3) Vt = Wv @ X^T + bv(row) -> fp16 [EMB, NROWS]
    gemm_h2<true><<<dim3(NROWS/BN, EMB/BM, 1), blk, SMEM>>>(
        wh + (size_t)2*EMB*EMB, EMB, 0, xh, EMB, 0, bs + 2*EMB, 0, 2,
        vth, NROWS, 0, EMB, 0);

    // 4) S[b] = q[b] @ k[b]^T -> fp16 (scale folded into softmax)
    gemm_h2<true><<<dim3(SEQ/BN, SEQ/BM, NB), blk, SMEM>>>(
        qh, EMB, (long long)SEQ*EMB, kh, EMB, (long long)SEQ*EMB, nullptr, 0, 0,
        sh, SEQ, (long long)SEQ*SEQ, EMB, 0);

    // 5) softmax rows
    softmax_h<<<NROWS, blk>>>(sh);

    // 6) out[b] = P[b] @ Vt[:, b*S:(b+1)*S]^T -> fp32
    gemm_h2<false><<<dim3(EMB/BN, SEQ/BM, NB), blk, SMEM>>>(
        sh, SEQ, (long long)SEQ*SEQ, vth, NROWS, 0, nullptr, 0, 0,
        out, EMB, (long long)SEQ*EMB, SEQ, SEQ);
}